// round 2
// baseline (speedup 1.0000x reference)
#include <cuda_runtime.h>
#include <math.h>

// Problem constants (fixed by the dataset)
#define kN    20000
#define kE    320000
#define kSED  768
#define kHC   512     // heads * channels layer 1
#define kH    4
#define kHID  128
#define kF    128     // layer-2 output channels

#define NEG_INF (-3.402823466e38f)

// ---------------- scratch (no allocation allowed) ----------------
__device__ float g_h1[kN * kHC];        // layer-1 pre-bias features (messages)
__device__ float g_h1act[kN * kHC];     // after agg + b1 + ELU
__device__ float g_h2[kN * kF];         // layer-2 pre-bias features
__device__ float g_c1[kHC];             // sent @ W1[768:1536]
__device__ float g_es1[kN * kH];
__device__ float g_ed1[kN * kH];
__device__ float g_es2[kN];
__device__ float g_ed2[kN];
__device__ int   g_deg[kN];
__device__ int   g_cursor[kN];
__device__ int   g_rowptr[kN + 1];
__device__ int   g_tscan[kN];
__device__ int   g_bsum[32];
__device__ int   g_boff[32];
__device__ int   g_srcs[kE];            // src node ids sorted by dst

// ---------------- CSR build ----------------
__global__ void k_zero_deg() {
    int i = blockIdx.x * blockDim.x + threadIdx.x;
    if (i < kN) g_deg[i] = 0;
}

__global__ void k_hist(const int* __restrict__ ei) {
    int e = blockIdx.x * blockDim.x + threadIdx.x;
    if (e < kE) atomicAdd(&g_deg[ei[kE + e]], 1);
}

__global__ void k_scan1() {
    __shared__ int sm[1024];
    int i = blockIdx.x * 1024 + threadIdx.x;
    int v = (i < kN) ? g_deg[i] : 0;
    sm[threadIdx.x] = v;
    __syncthreads();
    for (int off = 1; off < 1024; off <<= 1) {
        int t = (threadIdx.x >= off) ? sm[threadIdx.x - off] : 0;
        __syncthreads();
        sm[threadIdx.x] += t;
        __syncthreads();
    }
    if (i < kN) g_tscan[i] = sm[threadIdx.x];
    if (threadIdx.x == 1023) g_bsum[blockIdx.x] = sm[1023];
}

__global__ void k_scan2(int nb) {
    if (threadIdx.x == 0) {
        int run = 0;
        for (int b = 0; b < nb; b++) { g_boff[b] = run; run += g_bsum[b]; }
    }
}

__global__ void k_scan3() {
    int i = blockIdx.x * blockDim.x + threadIdx.x;
    if (i < kN) {
        int incl = g_tscan[i] + g_boff[i >> 10];
        g_rowptr[i + 1] = incl;
        g_cursor[i]     = incl - g_deg[i];
        if (i == 0) g_rowptr[0] = 0;
    }
}

__global__ void k_scatter(const int* __restrict__ ei) {
    int e = blockIdx.x * blockDim.x + threadIdx.x;
    if (e < kE) {
        int d = ei[kE + e];
        int pos = atomicAdd(&g_cursor[d], 1);
        g_srcs[pos] = ei[e];
    }
}

// ---------------- constant column bias: c1 = sent @ W1[768:1536] ----------------
__global__ void k_c1(const float* __restrict__ sent, const float* __restrict__ W1) {
    int j = blockIdx.x * blockDim.x + threadIdx.x;   // 0..511
    if (j >= kHC) return;
    float acc = 0.f;
    for (int k = 0; k < kSED; k++)
        acc += sent[k] * W1[(kSED + k) * kHC + j];
    g_c1[j] = acc;
}

// ---------------- tiled fp32 GEMM: C[M,N] = A[M,K] @ B[K,N] (+ colbias) ----------------
// BM=128, BN=128, BK=8, 256 threads, 8x8 per thread. K % 8 == 0, N % 128 == 0 assumed.
__device__ __forceinline__ void sgemm_body(
    const float* __restrict__ A, const float* __restrict__ B, float* __restrict__ C,
    int M, int N, int K, const float* __restrict__ colbias)
{
    __shared__ float As[8][128];
    __shared__ float Bs[8][128];

    int tid = threadIdx.x;
    int tx = tid & 15;          // 0..15 -> col micro-tile
    int ty = tid >> 4;          // 0..15 -> row micro-tile
    int rowBase = blockIdx.y * 128;
    int colBase = blockIdx.x * 128;

    int aRow = tid >> 1;              // 0..127
    int aCol = (tid & 1) << 2;        // 0 or 4
    int bRow = tid >> 5;              // 0..7
    int bCol = (tid & 31) << 2;       // 0..124

    float acc[8][8];
    #pragma unroll
    for (int i = 0; i < 8; i++)
        #pragma unroll
        for (int j = 0; j < 8; j++) acc[i][j] = 0.f;

    for (int k0 = 0; k0 < K; k0 += 8) {
        float4 av = make_float4(0.f, 0.f, 0.f, 0.f);
        int ar = rowBase + aRow;
        if (ar < M) av = *(const float4*)&A[(long)ar * K + k0 + aCol];
        As[aCol + 0][aRow] = av.x;
        As[aCol + 1][aRow] = av.y;
        As[aCol + 2][aRow] = av.z;
        As[aCol + 3][aRow] = av.w;

        float4 bv = *(const float4*)&B[(long)(k0 + bRow) * N + colBase + bCol];
        *(float4*)&Bs[bRow][bCol] = bv;
        __syncthreads();

        #pragma unroll
        for (int kk = 0; kk < 8; kk++) {
            float4 a0 = *(const float4*)&As[kk][ty * 8];
            float4 a1 = *(const float4*)&As[kk][ty * 8 + 4];
            float4 b0 = *(const float4*)&Bs[kk][tx * 8];
            float4 b1 = *(const float4*)&Bs[kk][tx * 8 + 4];
            float ar8[8] = {a0.x, a0.y, a0.z, a0.w, a1.x, a1.y, a1.z, a1.w};
            float br8[8] = {b0.x, b0.y, b0.z, b0.w, b1.x, b1.y, b1.z, b1.w};
            #pragma unroll
            for (int i = 0; i < 8; i++)
                #pragma unroll
                for (int j = 0; j < 8; j++)
                    acc[i][j] += ar8[i] * br8[j];
        }
        __syncthreads();
    }

    #pragma unroll
    for (int i = 0; i < 8; i++) {
        int r = rowBase + ty * 8 + i;
        if (r >= M) continue;
        #pragma unroll
        for (int j = 0; j < 8; j++) {
            int c = colBase + tx * 8 + j;
            float v = acc[i][j];
            if (colbias) v += colbias[c];
            C[(long)r * N + c] = v;
        }
    }
}

__global__ void k_gemm1(const float* __restrict__ x, const float* __restrict__ W1) {
    sgemm_body(x, W1, g_h1, kN, kHC, kSED, g_c1);
}
__global__ void k_gemm2(const float* __restrict__ W2) {
    sgemm_body(g_h1act, W2, g_h2, kN, kF, kHC, nullptr);
}

// ---------------- attention scalar dots ----------------
__global__ void k_dots1(const float* __restrict__ a_src, const float* __restrict__ a_dst) {
    int gw = (blockIdx.x * blockDim.x + threadIdx.x) >> 5;
    int lane = threadIdx.x & 31;
    if (gw >= kN * kH) return;
    int n = gw >> 2, h = gw & 3;
    const float* row = g_h1 + (long)n * kHC + h * kHID;
    const float* as = a_src + h * kHID;
    const float* ad = a_dst + h * kHID;
    float s1 = 0.f, s2 = 0.f;
    #pragma unroll
    for (int c = lane; c < kHID; c += 32) {
        float v = row[c];
        s1 += v * as[c];
        s2 += v * ad[c];
    }
    #pragma unroll
    for (int o = 16; o; o >>= 1) {
        s1 += __shfl_xor_sync(0xffffffffu, s1, o);
        s2 += __shfl_xor_sync(0xffffffffu, s2, o);
    }
    if (lane == 0) { g_es1[gw] = s1; g_ed1[gw] = s2; }
}

__global__ void k_dots2(const float* __restrict__ a_src, const float* __restrict__ a_dst) {
    int gw = (blockIdx.x * blockDim.x + threadIdx.x) >> 5;
    int lane = threadIdx.x & 31;
    if (gw >= kN) return;
    const float* row = g_h2 + (long)gw * kF;
    float s1 = 0.f, s2 = 0.f;
    #pragma unroll
    for (int c = lane; c < kF; c += 32) {
        float v = row[c];
        s1 += v * a_src[c];
        s2 += v * a_dst[c];
    }
    #pragma unroll
    for (int o = 16; o; o >>= 1) {
        s1 += __shfl_xor_sync(0xffffffffu, s1, o);
        s2 += __shfl_xor_sync(0xffffffffu, s2, o);
    }
    if (lane == 0) { g_es2[gw] = s1; g_ed2[gw] = s2; }
}

// ---------------- layer-1 aggregation: softmax over incoming edges, gather, +b1, ELU ----------------
__global__ void __launch_bounds__(512) k_agg1(const float* __restrict__ b1) {
    __shared__ float red[16][4];
    __shared__ float msm[4], rssm[4];
    __shared__ float alpha_sm[128 * 4];
    __shared__ int   src_sm[128];

    int v = blockIdx.x;
    int tid = threadIdx.x;
    int lane = tid & 31, wid = tid >> 5;
    int beg = g_rowptr[v], end = g_rowptr[v + 1];

    float ed0 = g_ed1[v * 4 + 0], ed1v = g_ed1[v * 4 + 1];
    float ed2v = g_ed1[v * 4 + 2], ed3v = g_ed1[v * 4 + 3];

    // pass 1: max
    float lm0 = NEG_INF, lm1 = NEG_INF, lm2 = NEG_INF, lm3 = NEG_INF;
    for (int j = beg + tid; j < end; j += 512) {
        int s = g_srcs[j];
        float4 es = *(const float4*)&g_es1[s * 4];
        float e0 = es.x + ed0;  e0 = e0 > 0.f ? e0 : 0.2f * e0;
        float e1 = es.y + ed1v; e1 = e1 > 0.f ? e1 : 0.2f * e1;
        float e2 = es.z + ed2v; e2 = e2 > 0.f ? e2 : 0.2f * e2;
        float e3 = es.w + ed3v; e3 = e3 > 0.f ? e3 : 0.2f * e3;
        lm0 = fmaxf(lm0, e0); lm1 = fmaxf(lm1, e1);
        lm2 = fmaxf(lm2, e2); lm3 = fmaxf(lm3, e3);
    }
    #pragma unroll
    for (int o = 16; o; o >>= 1) {
        lm0 = fmaxf(lm0, __shfl_xor_sync(0xffffffffu, lm0, o));
        lm1 = fmaxf(lm1, __shfl_xor_sync(0xffffffffu, lm1, o));
        lm2 = fmaxf(lm2, __shfl_xor_sync(0xffffffffu, lm2, o));
        lm3 = fmaxf(lm3, __shfl_xor_sync(0xffffffffu, lm3, o));
    }
    if (lane == 0) { red[wid][0] = lm0; red[wid][1] = lm1; red[wid][2] = lm2; red[wid][3] = lm3; }
    __syncthreads();
    if (tid < 4) {
        float m = red[0][tid];
        #pragma unroll
        for (int w = 1; w < 16; w++) m = fmaxf(m, red[w][tid]);
        msm[tid] = m;
    }
    __syncthreads();
    float m0 = msm[0], m1 = msm[1], m2 = msm[2], m3 = msm[3];

    // pass 2: sum of exp
    float ls0 = 0.f, ls1 = 0.f, ls2 = 0.f, ls3 = 0.f;
    for (int j = beg + tid; j < end; j += 512) {
        int s = g_srcs[j];
        float4 es = *(const float4*)&g_es1[s * 4];
        float e0 = es.x + ed0;  e0 = e0 > 0.f ? e0 : 0.2f * e0;
        float e1 = es.y + ed1v; e1 = e1 > 0.f ? e1 : 0.2f * e1;
        float e2 = es.z + ed2v; e2 = e2 > 0.f ? e2 : 0.2f * e2;
        float e3 = es.w + ed3v; e3 = e3 > 0.f ? e3 : 0.2f * e3;
        ls0 += __expf(e0 - m0); ls1 += __expf(e1 - m1);
        ls2 += __expf(e2 - m2); ls3 += __expf(e3 - m3);
    }
    #pragma unroll
    for (int o = 16; o; o >>= 1) {
        ls0 += __shfl_xor_sync(0xffffffffu, ls0, o);
        ls1 += __shfl_xor_sync(0xffffffffu, ls1, o);
        ls2 += __shfl_xor_sync(0xffffffffu, ls2, o);
        ls3 += __shfl_xor_sync(0xffffffffu, ls3, o);
    }
    if (lane == 0) { red[wid][0] = ls0; red[wid][1] = ls1; red[wid][2] = ls2; red[wid][3] = ls3; }
    __syncthreads();
    if (tid < 4) {
        float s = 0.f;
        #pragma unroll
        for (int w = 0; w < 16; w++) s += red[w][tid];
        rssm[tid] = 1.f / (s + 1e-16f);
    }
    __syncthreads();

    // pass 3: weighted gather (chunks of 128 edges)
    int h = tid >> 7, c = tid & 127;
    (void)c;
    float acc = 0.f;
    for (int cb = beg; cb < end; cb += 128) {
        int cn = min(128, end - cb);
        for (int idx = tid; idx < cn * 4; idx += 512) {
            int j = idx >> 2, hh = idx & 3;
            int s = g_srcs[cb + j];
            float e = g_es1[s * 4 + hh] + g_ed1[v * 4 + hh];
            e = e > 0.f ? e : 0.2f * e;
            alpha_sm[(j << 2) + hh] = __expf(e - msm[hh]) * rssm[hh];
            if (hh == 0) src_sm[j] = s;
        }
        __syncthreads();
        for (int j = 0; j < cn; j++)
            acc += alpha_sm[(j << 2) + h] * g_h1[(long)src_sm[j] * kHC + tid];
        __syncthreads();
    }
    float o = acc + b1[tid];
    g_h1act[(long)v * kHC + tid] = o > 0.f ? o : (__expf(o) - 1.f);   // ELU(alpha=1)
}

// ---------------- layer-2 aggregation (single head), +b2, write out ----------------
__global__ void __launch_bounds__(128) k_agg2(const float* __restrict__ b2, float* __restrict__ out) {
    __shared__ float red[4];
    __shared__ float msm1, rssm1;
    __shared__ float alpha_sm[256];
    __shared__ int   src_sm[256];

    int v = blockIdx.x;
    int tid = threadIdx.x;
    int lane = tid & 31, wid = tid >> 5;
    int beg = g_rowptr[v], end = g_rowptr[v + 1];
    float edv = g_ed2[v];

    float lm = NEG_INF;
    for (int j = beg + tid; j < end; j += 128) {
        float e = g_es2[g_srcs[j]] + edv;
        e = e > 0.f ? e : 0.2f * e;
        lm = fmaxf(lm, e);
    }
    #pragma unroll
    for (int o = 16; o; o >>= 1) lm = fmaxf(lm, __shfl_xor_sync(0xffffffffu, lm, o));
    if (lane == 0) red[wid] = lm;
    __syncthreads();
    if (tid == 0) {
        float m = red[0];
        #pragma unroll
        for (int w = 1; w < 4; w++) m = fmaxf(m, red[w]);
        msm1 = m;
    }
    __syncthreads();
    float m = msm1;

    float ls = 0.f;
    for (int j = beg + tid; j < end; j += 128) {
        float e = g_es2[g_srcs[j]] + edv;
        e = e > 0.f ? e : 0.2f * e;
        ls += __expf(e - m);
    }
    #pragma unroll
    for (int o = 16; o; o >>= 1) ls += __shfl_xor_sync(0xffffffffu, ls, o);
    if (lane == 0) red[wid] = ls;
    __syncthreads();
    if (tid == 0) rssm1 = 1.f / (red[0] + red[1] + red[2] + red[3] + 1e-16f);
    __syncthreads();
    float rs = rssm1;

    float acc = 0.f;
    for (int cb = beg; cb < end; cb += 256) {
        int cn = min(256, end - cb);
        for (int idx = tid; idx < cn; idx += 128) {
            int s = g_srcs[cb + idx];
            float e = g_es2[s] + edv;
            e = e > 0.f ? e : 0.2f * e;
            alpha_sm[idx] = __expf(e - m) * rs;
            src_sm[idx] = s;
        }
        __syncthreads();
        for (int j = 0; j < cn; j++)
            acc += alpha_sm[j] * g_h2[(long)src_sm[j] * kF + tid];
        __syncthreads();
    }
    out[(long)v * kF + tid] = acc + b2[tid];
}

// ---------------- launch ----------------
extern "C" void kernel_launch(void* const* d_in, const int* in_sizes, int n_in,
                              void* d_out, int out_size) {
    const float* x    = (const float*)d_in[0];
    const int*   ei   = (const int*)d_in[1];
    const float* sent = (const float*)d_in[2];
    const float* W1   = (const float*)d_in[3];
    const float* a1s  = (const float*)d_in[4];
    const float* a1d  = (const float*)d_in[5];
    const float* b1   = (const float*)d_in[6];
    const float* W2   = (const float*)d_in[7];
    const float* a2s  = (const float*)d_in[8];
    const float* a2d  = (const float*)d_in[9];
    const float* b2   = (const float*)d_in[10];
    float* out = (float*)d_out;

    // CSR build (shared by both layers)
    k_zero_deg<<<(kN + 255) / 256, 256>>>();
    k_hist<<<(kE + 255) / 256, 256>>>(ei);
    k_scan1<<<(kN + 1023) / 1024, 1024>>>();
    k_scan2<<<1, 32>>>((kN + 1023) / 1024);
    k_scan3<<<(kN + 255) / 256, 256>>>();
    k_scatter<<<(kE + 255) / 256, 256>>>(ei);

    // layer 1
    k_c1<<<2, 256>>>(sent, W1);
    {
        dim3 g(kHC / 128, (kN + 127) / 128);
        k_gemm1<<<g, 256>>>(x, W1);
    }
    k_dots1<<<(kN * kH * 32 + 255) / 256, 256>>>(a1s, a1d);
    k_agg1<<<kN, 512>>>(b1);

    // layer 2
    {
        dim3 g(kF / 128, (kN + 127) / 128);
        k_gemm2<<<g, 256>>>(W2);
    }
    k_dots2<<<(kN * 32 + 255) / 256, 256>>>(a2s, a2d);
    k_agg2<<<kN, 128>>>(b2, out);
}

// round 5
// speedup vs baseline: 1.2662x; 1.2662x over previous
#include <cuda_runtime.h>
#include <math.h>

// Problem constants (fixed by the dataset)
#define kN    20000
#define kE    320000
#define kSED  768
#define kHC   512     // heads * channels layer 1
#define kH    4
#define kHID  128
#define kF    128     // layer-2 output channels

#define NEG_INF (-3.402823466e38f)

// ---------------- scratch (no allocation allowed) ----------------
__device__ float g_h1[kN * kHC];        // layer-1 pre-bias features (messages)
__device__ float g_h1act[kN * kHC];     // after agg + b1 + ELU
__device__ float g_h2[kN * kF];         // layer-2 pre-bias features
__device__ float g_c1[kHC];             // sent @ W1[768:1536]
__device__ float g_es1[kN * kH];
__device__ float g_ed1[kN * kH];
__device__ float g_es2[kN];
__device__ float g_ed2[kN];
__device__ int   g_deg[kN];
__device__ int   g_cursor[kN];
__device__ int   g_rowptr[kN + 1];
__device__ int   g_tscan[kN];
__device__ int   g_bsum[32];
__device__ int   g_boff[32];
__device__ int   g_srcs[kE];            // src node ids sorted by dst

// ---------------- CSR build ----------------
__global__ void k_zero_deg() {
    int i = blockIdx.x * blockDim.x + threadIdx.x;
    if (i < kN) g_deg[i] = 0;
}

__global__ void k_hist(const int* __restrict__ ei) {
    int e = blockIdx.x * blockDim.x + threadIdx.x;
    if (e < kE) atomicAdd(&g_deg[ei[kE + e]], 1);
}

__global__ void k_scan1() {
    __shared__ int sm[1024];
    int i = blockIdx.x * 1024 + threadIdx.x;
    int v = (i < kN) ? g_deg[i] : 0;
    sm[threadIdx.x] = v;
    __syncthreads();
    for (int off = 1; off < 1024; off <<= 1) {
        int t = (threadIdx.x >= off) ? sm[threadIdx.x - off] : 0;
        __syncthreads();
        sm[threadIdx.x] += t;
        __syncthreads();
    }
    if (i < kN) g_tscan[i] = sm[threadIdx.x];
    if (threadIdx.x == 1023) g_bsum[blockIdx.x] = sm[1023];
}

__global__ void k_scan2(int nb) {
    if (threadIdx.x == 0) {
        int run = 0;
        for (int b = 0; b < nb; b++) { g_boff[b] = run; run += g_bsum[b]; }
    }
}

__global__ void k_scan3() {
    int i = blockIdx.x * blockDim.x + threadIdx.x;
    if (i < kN) {
        int incl = g_tscan[i] + g_boff[i >> 10];
        g_rowptr[i + 1] = incl;
        g_cursor[i]     = incl - g_deg[i];
        if (i == 0) g_rowptr[0] = 0;
    }
}

__global__ void k_scatter(const int* __restrict__ ei) {
    int e = blockIdx.x * blockDim.x + threadIdx.x;
    if (e < kE) {
        int d = ei[kE + e];
        int pos = atomicAdd(&g_cursor[d], 1);
        g_srcs[pos] = ei[e];
    }
}

// ---------------- constant column bias: c1 = sent @ W1[768:1536] ----------------
__global__ void k_c1(const float* __restrict__ sent, const float* __restrict__ W1) {
    int j = blockIdx.x * blockDim.x + threadIdx.x;   // 0..511
    if (j >= kHC) return;
    float acc = 0.f;
    for (int k = 0; k < kSED; k++)
        acc += sent[k] * W1[(kSED + k) * kHC + j];
    g_c1[j] = acc;
}

// ---------------- tf32 tensor-core GEMM with 2-term split (fp32-accurate) ----------------
// C[M,N] = A[M,K] @ B[K,N] (+ colbias). Block tile 128x128, k-tile 16,
// 256 threads = 8 warps of 64x32. D = Ah*Bh + Ah*Bl + Al*Bh.
#define GBM 128
#define GBN 128
#define GBK 16
#define APAD 20     // k-dim pad for A smem: (20*g + tg) % 32 distinct over the warp
#define BPAD 136    // n-dim pad for B smem: (136*tg + g) % 32 = (8*tg + g) distinct

__device__ __forceinline__ unsigned f2tf(float x) {
    unsigned r;
    asm("cvt.rna.tf32.f32 %0, %1;" : "=r"(r) : "f"(x));
    return r;
}

__device__ __forceinline__ void mma_tf32(float* c,
    unsigned a0, unsigned a1, unsigned a2, unsigned a3,
    unsigned b0, unsigned b1)
{
    asm volatile(
        "mma.sync.aligned.m16n8k8.row.col.f32.tf32.tf32.f32 "
        "{%0,%1,%2,%3},{%4,%5,%6,%7},{%8,%9},{%0,%1,%2,%3};"
        : "+f"(c[0]), "+f"(c[1]), "+f"(c[2]), "+f"(c[3])
        : "r"(a0), "r"(a1), "r"(a2), "r"(a3), "r"(b0), "r"(b1));
}

__global__ void __launch_bounds__(256) k_mma_gemm(
    const float* __restrict__ A, const float* __restrict__ B, float* __restrict__ C,
    int M, int N, int K, const float* __restrict__ colbias)
{
    __shared__ float Ah[GBM][APAD];
    __shared__ float Al[GBM][APAD];
    __shared__ float Bh[GBK][BPAD];
    __shared__ float Bl[GBK][BPAD];

    int tid  = threadIdx.x;
    int wid  = tid >> 5, lane = tid & 31;
    int g    = lane >> 2, tg = lane & 3;
    int warpM = (wid >> 2) * 64;   // 0 or 64
    int warpN = (wid & 3) * 32;    // 0,32,64,96
    int rowBase = blockIdx.y * GBM;
    int colBase = blockIdx.x * GBN;

    float acc[4][4][4];
    #pragma unroll
    for (int i = 0; i < 4; i++)
        #pragma unroll
        for (int j = 0; j < 4; j++)
            #pragma unroll
            for (int r = 0; r < 4; r++) acc[i][j][r] = 0.f;

    for (int k0 = 0; k0 < K; k0 += GBK) {
        // --- load + split A tile: 128x16 = 512 float4, 2 per thread ---
        #pragma unroll
        for (int it = 0; it < 2; it++) {
            int idx = tid + it * 256;
            int m = idx >> 2, k4 = (idx & 3) << 2;
            int gm = rowBase + m;
            float4 v = make_float4(0.f, 0.f, 0.f, 0.f);
            if (gm < M) v = *(const float4*)&A[(long)gm * K + k0 + k4];
            float hx = __uint_as_float(f2tf(v.x));
            float hy = __uint_as_float(f2tf(v.y));
            float hz = __uint_as_float(f2tf(v.z));
            float hw = __uint_as_float(f2tf(v.w));
            *(float4*)&Ah[m][k4] = make_float4(hx, hy, hz, hw);
            *(float4*)&Al[m][k4] = make_float4(
                __uint_as_float(f2tf(v.x - hx)),
                __uint_as_float(f2tf(v.y - hy)),
                __uint_as_float(f2tf(v.z - hz)),
                __uint_as_float(f2tf(v.w - hw)));
        }
        // --- load + split B tile: 16x128 = 512 float4, 2 per thread ---
        #pragma unroll
        for (int it = 0; it < 2; it++) {
            int idx = tid + it * 256;
            int kk = idx >> 5, n4 = (idx & 31) << 2;
            float4 v = *(const float4*)&B[(long)(k0 + kk) * N + colBase + n4];
            float hx = __uint_as_float(f2tf(v.x));
            float hy = __uint_as_float(f2tf(v.y));
            float hz = __uint_as_float(f2tf(v.z));
            float hw = __uint_as_float(f2tf(v.w));
            *(float4*)&Bh[kk][n4] = make_float4(hx, hy, hz, hw);
            *(float4*)&Bl[kk][n4] = make_float4(
                __uint_as_float(f2tf(v.x - hx)),
                __uint_as_float(f2tf(v.y - hy)),
                __uint_as_float(f2tf(v.z - hz)),
                __uint_as_float(f2tf(v.w - hw)));
        }
        __syncthreads();

        #pragma unroll
        for (int ks = 0; ks < GBK; ks += 8) {
            unsigned ah[4][4], al[4][4];
            #pragma unroll
            for (int i = 0; i < 4; i++) {
                int rm = warpM + i * 16;
                ah[i][0] = __float_as_uint(Ah[rm + g    ][ks + tg    ]);
                ah[i][1] = __float_as_uint(Ah[rm + g + 8][ks + tg    ]);
                ah[i][2] = __float_as_uint(Ah[rm + g    ][ks + tg + 4]);
                ah[i][3] = __float_as_uint(Ah[rm + g + 8][ks + tg + 4]);
                al[i][0] = __float_as_uint(Al[rm + g    ][ks + tg    ]);
                al[i][1] = __float_as_uint(Al[rm + g + 8][ks + tg    ]);
                al[i][2] = __float_as_uint(Al[rm + g    ][ks + tg + 4]);
                al[i][3] = __float_as_uint(Al[rm + g + 8][ks + tg + 4]);
            }
            unsigned bh[4][2], bl[4][2];
            #pragma unroll
            for (int j = 0; j < 4; j++) {
                int cn = warpN + j * 8;
                bh[j][0] = __float_as_uint(Bh[ks + tg    ][cn + g]);
                bh[j][1] = __float_as_uint(Bh[ks + tg + 4][cn + g]);
                bl[j][0] = __float_as_uint(Bl[ks + tg    ][cn + g]);
                bl[j][1] = __float_as_uint(Bl[ks + tg + 4][cn + g]);
            }
            #pragma unroll
            for (int i = 0; i < 4; i++)
                #pragma unroll
                for (int j = 0; j < 4; j++) {
                    mma_tf32(acc[i][j], ah[i][0], ah[i][1], ah[i][2], ah[i][3], bh[j][0], bh[j][1]);
                    mma_tf32(acc[i][j], ah[i][0], ah[i][1], ah[i][2], ah[i][3], bl[j][0], bl[j][1]);
                    mma_tf32(acc[i][j], al[i][0], al[i][1], al[i][2], al[i][3], bh[j][0], bh[j][1]);
                }
        }
        __syncthreads();
    }

    // epilogue
    #pragma unroll
    for (int i = 0; i < 4; i++) {
        int r0 = rowBase + warpM + i * 16 + g;
        int r1 = r0 + 8;
        #pragma unroll
        for (int j = 0; j < 4; j++) {
            int c = colBase + warpN + j * 8 + tg * 2;
            float2 v0 = make_float2(acc[i][j][0], acc[i][j][1]);
            float2 v1 = make_float2(acc[i][j][2], acc[i][j][3]);
            if (colbias) {
                float cb0 = colbias[c], cb1 = colbias[c + 1];
                v0.x += cb0; v0.y += cb1;
                v1.x += cb0; v1.y += cb1;
            }
            if (r0 < M) *(float2*)&C[(long)r0 * N + c] = v0;
            if (r1 < M) *(float2*)&C[(long)r1 * N + c] = v1;
        }
    }
}

// ---------------- attention scalar dots ----------------
__global__ void k_dots1(const float* __restrict__ a_src, const float* __restrict__ a_dst) {
    int gw = (blockIdx.x * blockDim.x + threadIdx.x) >> 5;
    int lane = threadIdx.x & 31;
    if (gw >= kN * kH) return;
    int n = gw >> 2, h = gw & 3;
    const float* row = g_h1 + (long)n * kHC + h * kHID;
    const float* as = a_src + h * kHID;
    const float* ad = a_dst + h * kHID;
    float s1 = 0.f, s2 = 0.f;
    #pragma unroll
    for (int c = lane; c < kHID; c += 32) {
        float v = row[c];
        s1 += v * as[c];
        s2 += v * ad[c];
    }
    #pragma unroll
    for (int o = 16; o; o >>= 1) {
        s1 += __shfl_xor_sync(0xffffffffu, s1, o);
        s2 += __shfl_xor_sync(0xffffffffu, s2, o);
    }
    if (lane == 0) { g_es1[gw] = s1; g_ed1[gw] = s2; }
}

__global__ void k_dots2(const float* __restrict__ a_src, const float* __restrict__ a_dst) {
    int gw = (blockIdx.x * blockDim.x + threadIdx.x) >> 5;
    int lane = threadIdx.x & 31;
    if (gw >= kN) return;
    const float* row = g_h2 + (long)gw * kF;
    float s1 = 0.f, s2 = 0.f;
    #pragma unroll
    for (int c = lane; c < kF; c += 32) {
        float v = row[c];
        s1 += v * a_src[c];
        s2 += v * a_dst[c];
    }
    #pragma unroll
    for (int o = 16; o; o >>= 1) {
        s1 += __shfl_xor_sync(0xffffffffu, s1, o);
        s2 += __shfl_xor_sync(0xffffffffu, s2, o);
    }
    if (lane == 0) { g_es2[gw] = s1; g_ed2[gw] = s2; }
}

// ---------------- layer-1 aggregation: softmax over incoming edges, gather, +b1, ELU ----------------
__global__ void __launch_bounds__(512) k_agg1(const float* __restrict__ b1) {
    __shared__ float red[16][4];
    __shared__ float msm[4], rssm[4];
    __shared__ float alpha_sm[128 * 4];
    __shared__ int   src_sm[128];

    int v = blockIdx.x;
    int tid = threadIdx.x;
    int lane = tid & 31, wid = tid >> 5;
    int beg = g_rowptr[v], end = g_rowptr[v + 1];

    float ed0 = g_ed1[v * 4 + 0], ed1v = g_ed1[v * 4 + 1];
    float ed2v = g_ed1[v * 4 + 2], ed3v = g_ed1[v * 4 + 3];

    // pass 1: max
    float lm0 = NEG_INF, lm1 = NEG_INF, lm2 = NEG_INF, lm3 = NEG_INF;
    for (int j = beg + tid; j < end; j += 512) {
        int s = g_srcs[j];
        float4 es = *(const float4*)&g_es1[s * 4];
        float e0 = es.x + ed0;  e0 = e0 > 0.f ? e0 : 0.2f * e0;
        float e1 = es.y + ed1v; e1 = e1 > 0.f ? e1 : 0.2f * e1;
        float e2 = es.z + ed2v; e2 = e2 > 0.f ? e2 : 0.2f * e2;
        float e3 = es.w + ed3v; e3 = e3 > 0.f ? e3 : 0.2f * e3;
        lm0 = fmaxf(lm0, e0); lm1 = fmaxf(lm1, e1);
        lm2 = fmaxf(lm2, e2); lm3 = fmaxf(lm3, e3);
    }
    #pragma unroll
    for (int o = 16; o; o >>= 1) {
        lm0 = fmaxf(lm0, __shfl_xor_sync(0xffffffffu, lm0, o));
        lm1 = fmaxf(lm1, __shfl_xor_sync(0xffffffffu, lm1, o));
        lm2 = fmaxf(lm2, __shfl_xor_sync(0xffffffffu, lm2, o));
        lm3 = fmaxf(lm3, __shfl_xor_sync(0xffffffffu, lm3, o));
    }
    if (lane == 0) { red[wid][0] = lm0; red[wid][1] = lm1; red[wid][2] = lm2; red[wid][3] = lm3; }
    __syncthreads();
    if (tid < 4) {
        float m = red[0][tid];
        #pragma unroll
        for (int w = 1; w < 16; w++) m = fmaxf(m, red[w][tid]);
        msm[tid] = m;
    }
    __syncthreads();
    float m0 = msm[0], m1 = msm[1], m2 = msm[2], m3 = msm[3];

    // pass 2: sum of exp
    float ls0 = 0.f, ls1 = 0.f, ls2 = 0.f, ls3 = 0.f;
    for (int j = beg + tid; j < end; j += 512) {
        int s = g_srcs[j];
        float4 es = *(const float4*)&g_es1[s * 4];
        float e0 = es.x + ed0;  e0 = e0 > 0.f ? e0 : 0.2f * e0;
        float e1 = es.y + ed1v; e1 = e1 > 0.f ? e1 : 0.2f * e1;
        float e2 = es.z + ed2v; e2 = e2 > 0.f ? e2 : 0.2f * e2;
        float e3 = es.w + ed3v; e3 = e3 > 0.f ? e3 : 0.2f * e3;
        ls0 += __expf(e0 - m0); ls1 += __expf(e1 - m1);
        ls2 += __expf(e2 - m2); ls3 += __expf(e3 - m3);
    }
    #pragma unroll
    for (int o = 16; o; o >>= 1) {
        ls0 += __shfl_xor_sync(0xffffffffu, ls0, o);
        ls1 += __shfl_xor_sync(0xffffffffu, ls1, o);
        ls2 += __shfl_xor_sync(0xffffffffu, ls2, o);
        ls3 += __shfl_xor_sync(0xffffffffu, ls3, o);
    }
    if (lane == 0) { red[wid][0] = ls0; red[wid][1] = ls1; red[wid][2] = ls2; red[wid][3] = ls3; }
    __syncthreads();
    if (tid < 4) {
        float s = 0.f;
        #pragma unroll
        for (int w = 0; w < 16; w++) s += red[w][tid];
        rssm[tid] = 1.f / (s + 1e-16f);
    }
    __syncthreads();

    // pass 3: weighted gather (chunks of 128 edges)
    int h = tid >> 7;
    float acc = 0.f;
    for (int cb = beg; cb < end; cb += 128) {
        int cn = min(128, end - cb);
        for (int idx = tid; idx < cn * 4; idx += 512) {
            int j = idx >> 2, hh = idx & 3;
            int s = g_srcs[cb + j];
            float e = g_es1[s * 4 + hh] + g_ed1[v * 4 + hh];
            e = e > 0.f ? e : 0.2f * e;
            alpha_sm[(j << 2) + hh] = __expf(e - msm[hh]) * rssm[hh];
            if (hh == 0) src_sm[j] = s;
        }
        __syncthreads();
        for (int j = 0; j < cn; j++)
            acc += alpha_sm[(j << 2) + h] * g_h1[(long)src_sm[j] * kHC + tid];
        __syncthreads();
    }
    float o = acc + b1[tid];
    g_h1act[(long)v * kHC + tid] = o > 0.f ? o : (__expf(o) - 1.f);   // ELU(alpha=1)
}

// ---------------- layer-2 aggregation (single head), +b2, write out ----------------
__global__ void __launch_bounds__(128) k_agg2(const float* __restrict__ b2, float* __restrict__ out) {
    __shared__ float red[4];
    __shared__ float msm1, rssm1;
    __shared__ float alpha_sm[256];
    __shared__ int   src_sm[256];

    int v = blockIdx.x;
    int tid = threadIdx.x;
    int lane = tid & 31, wid = tid >> 5;
    int beg = g_rowptr[v], end = g_rowptr[v + 1];
    float edv = g_ed2[v];

    float lm = NEG_INF;
    for (int j = beg + tid; j < end; j += 128) {
        float e = g_es2[g_srcs[j]] + edv;
        e = e > 0.f ? e : 0.2f * e;
        lm = fmaxf(lm, e);
    }
    #pragma unroll
    for (int o = 16; o; o >>= 1) lm = fmaxf(lm, __shfl_xor_sync(0xffffffffu, lm, o));
    if (lane == 0) red[wid] = lm;
    __syncthreads();
    if (tid == 0) {
        float m = red[0];
        #pragma unroll
        for (int w = 1; w < 4; w++) m = fmaxf(m, red[w]);
        msm1 = m;
    }
    __syncthreads();
    float m = msm1;

    float ls = 0.f;
    for (int j = beg + tid; j < end; j += 128) {
        float e = g_es2[g_srcs[j]] + edv;
        e = e > 0.f ? e : 0.2f * e;
        ls += __expf(e - m);
    }
    #pragma unroll
    for (int o = 16; o; o >>= 1) ls += __shfl_xor_sync(0xffffffffu, ls, o);
    if (lane == 0) red[wid] = ls;
    __syncthreads();
    if (tid == 0) rssm1 = 1.f / (red[0] + red[1] + red[2] + red[3] + 1e-16f);
    __syncthreads();
    float rs = rssm1;

    float acc = 0.f;
    for (int cb = beg; cb < end; cb += 256) {
        int cn = min(256, end - cb);
        for (int idx = tid; idx < cn; idx += 128) {
            int s = g_srcs[cb + idx];
            float e = g_es2[s] + edv;
            e = e > 0.f ? e : 0.2f * e;
            alpha_sm[idx] = __expf(e - m) * rs;
            src_sm[idx] = s;
        }
        __syncthreads();
        for (int j = 0; j < cn; j++)
            acc += alpha_sm[j] * g_h2[(long)src_sm[j] * kF + tid];
        __syncthreads();
    }
    out[(long)v * kF + tid] = acc + b2[tid];
}

// ---------------- launch ----------------
extern "C" void kernel_launch(void* const* d_in, const int* in_sizes, int n_in,
                              void* d_out, int out_size) {
    const float* x    = (const float*)d_in[0];
    const int*   ei   = (const int*)d_in[1];
    const float* sent = (const float*)d_in[2];
    const float* W1   = (const float*)d_in[3];
    const float* a1s  = (const float*)d_in[4];
    const float* a1d  = (const float*)d_in[5];
    const float* b1   = (const float*)d_in[6];
    const float* W2   = (const float*)d_in[7];
    const float* a2s  = (const float*)d_in[8];
    const float* a2d  = (const float*)d_in[9];
    const float* b2   = (const float*)d_in[10];
    float* out = (float*)d_out;

    // CSR build (shared by both layers)
    k_zero_deg<<<(kN + 255) / 256, 256>>>();
    k_hist<<<(kE + 255) / 256, 256>>>(ei);
    k_scan1<<<(kN + 1023) / 1024, 1024>>>();
    k_scan2<<<1, 32>>>((kN + 1023) / 1024);
    k_scan3<<<(kN + 255) / 256, 256>>>();
    k_scatter<<<(kE + 255) / 256, 256>>>(ei);

    // layer 1
    k_c1<<<2, 256>>>(sent, W1);
    {
        float* c1ptr = nullptr;
        cudaGetSymbolAddress((void**)&c1ptr, g_c1);
        float* h1ptr = nullptr;
        cudaGetSymbolAddress((void**)&h1ptr, g_h1);
        dim3 g(kHC / 128, (kN + 127) / 128);
        k_mma_gemm<<<g, 256>>>(x, W1, h1ptr, kN, kHC, kSED, c1ptr);
    }
    k_dots1<<<(kN * kH * 32 + 255) / 256, 256>>>(a1s, a1d);
    k_agg1<<<kN, 512>>>(b1);

    // layer 2
    {
        float* h1aptr = nullptr;
        cudaGetSymbolAddress((void**)&h1aptr, g_h1act);
        float* h2ptr = nullptr;
        cudaGetSymbolAddress((void**)&h2ptr, g_h2);
        dim3 g(kF / 128, (kN + 127) / 128);
        k_mma_gemm<<<g, 256>>>(h1aptr, W2, h2ptr, kN, kF, kHC, nullptr);
    }
    k_dots2<<<(kN * 32 + 255) / 256, 256>>>(a2s, a2d);
    k_agg2<<<kN, 128>>>(b2, out);
}